// round 16
// baseline (speedup 1.0000x reference)
#include <cuda_runtime.h>
#include <cstdint>

#define B_  64
#define P_  2048
#define D_  1024
#define TILE_M 64
#define THREADS 128
#define KC 32
#define NSTAGE (D_ / KC)        /* 32 stages */
#define PITCH 80                /* 5 16B-units/row: 4 data + 1 pad; 5 coprime 8 */
#define A_OFF 0
#define B_OFF (TILE_M * PITCH)  /* 5120 */
#define STAGE_B (B_OFF + B_ * PITCH)       /* 10240 */
#define SMEM_BYTES (2 * STAGE_B)           /* 20480 dynamic */
#define NCTAS ((P_ / TILE_M) * B_)         /* 2048 */

__device__ unsigned int g_key[B_ * B_];    /* order-preserving keys; 0 == -inf */
__device__ unsigned int g_count;           /* last-CTA counter; resets itself  */
__device__ __align__(16) unsigned short g_bh[B_ * D_];   /* B in fp16, precomputed */

__device__ __forceinline__ uint32_t smem_u32(const void* p) {
    uint32_t a;
    asm("{ .reg .u64 t; cvta.to.shared.u64 t, %1; cvt.u32.u64 %0, t; }" : "=r"(a) : "l"(p));
    return a;
}
/* one float4 (k 4p..4p+3) -> 4 fp16 = 8B @addr */
__device__ __forceinline__ void cvt_sts4h(uint32_t addr, float4 v) {
    uint32_t h0, h1;
    asm("cvt.rn.f16x2.f32 %0, %1, %2;" : "=r"(h0) : "f"(v.y), "f"(v.x));
    asm("cvt.rn.f16x2.f32 %0, %1, %2;" : "=r"(h1) : "f"(v.w), "f"(v.z));
    asm volatile("st.shared.v2.b32 [%0], {%1,%2};" :: "r"(addr), "r"(h0), "r"(h1) : "memory");
}
__device__ __forceinline__ void cp16(uint32_t smemAddr, const void* gptr) {
    asm volatile("cp.async.cg.shared.global [%0], [%1], 16;"
                 :: "r"(smemAddr), "l"(gptr) : "memory");
}
__device__ __forceinline__ void ldsm4(uint32_t* r, uint32_t addr) {
    asm volatile("ldmatrix.sync.aligned.m8n8.x4.shared.b16 {%0,%1,%2,%3}, [%4];"
                 : "=r"(r[0]), "=r"(r[1]), "=r"(r[2]), "=r"(r[3]) : "r"(addr));
}
__device__ __forceinline__ void mma16816(float* c, const uint32_t* a, const uint32_t* b) {
    asm volatile(
        "mma.sync.aligned.m16n8k16.row.col.f32.f16.f16.f32 "
        "{%0,%1,%2,%3}, {%4,%5,%6,%7}, {%8,%9}, {%0,%1,%2,%3};"
        : "+f"(c[0]), "+f"(c[1]), "+f"(c[2]), "+f"(c[3])
        : "r"(a[0]), "r"(a[1]), "r"(a[2]), "r"(a[3]), "r"(b[0]), "r"(b[1]));
}

/* prologue: B (64x1024 fp32) -> g_bh fp16. grid 32 x 256 thr, 8 elems/thread */
__global__ void convb_kernel(const float* __restrict__ dis) {
    const int idx = blockIdx.x * 256 + threadIdx.x;   /* 8192 threads */
    const float4 v0 = *(const float4*)(dis + idx * 8);
    const float4 v1 = *(const float4*)(dis + idx * 8 + 4);
    uint32_t h0, h1, h2, h3;
    asm("cvt.rn.f16x2.f32 %0, %1, %2;" : "=r"(h0) : "f"(v0.y), "f"(v0.x));
    asm("cvt.rn.f16x2.f32 %0, %1, %2;" : "=r"(h1) : "f"(v0.w), "f"(v0.z));
    asm("cvt.rn.f16x2.f32 %0, %1, %2;" : "=r"(h2) : "f"(v1.y), "f"(v1.x));
    asm("cvt.rn.f16x2.f32 %0, %1, %2;" : "=r"(h3) : "f"(v1.w), "f"(v1.z));
    ((uint4*)g_bh)[idx] = make_uint4(h0, h1, h2, h3);
}

/* Grid (32,64), 128 thr, 5 CTAs/SM. sim[64p x 64c] single-pass fp16 HMMA.
   A: LDG fp32 -> cvt -> STS (double-buffered). B: cp.async.cg of precomputed
   fp16 (L1-bypass read, no regs/cvt/STS). Warp stagger; per-col max -> g_key;
   fused last-CTA hinge loss.
   Row layout (PITCH=80): 16B units {k0-7, k8-15, k16-23, k24-31, pad}. */
__global__ __launch_bounds__(THREADS, 5)
void fused_kernel(const float* __restrict__ im,
                  const void* __restrict__ lblRaw, float* __restrict__ out) {
    extern __shared__ __align__(128) char smem[];
    __shared__ int s_last, s_is64;
    __shared__ float rr[3][4];
    const uint32_t sb = smem_u32(smem);
    const int tid = threadIdx.x, lid = tid & 31, wid = tid >> 5;
    const int wm = wid & 1, wn = wid >> 1;
    const int b = blockIdx.y, pt = blockIdx.x;

    /* A staging: row r0 = tid>>3, part p0 = tid&7; 8 lanes per 128B gmem line */
    const int r0 = tid >> 3, p0 = tid & 7;
    const float* aG = im + ((size_t)(b * P_ + pt * TILE_M + r0)) * D_ + p0 * 4;
    const uint32_t aS = sb + A_OFF + (uint32_t)(r0 * PITCH + p0 * 8);

    /* B cp.async: row rb = tid>>1; thread handles 2 16B units (tid&1 selects pair) */
    const int rb = tid >> 1, ub = (tid & 1) * 2;
    const unsigned short* bGh = g_bh + (size_t)rb * D_ + ub * 8;
    const uint32_t bS = sb + B_OFF + (uint32_t)(rb * PITCH + ub * 16);

    /* ldmatrix lane bases (k8-15 unit = +16; sub s = +s*32) */
    const uint32_t aLd = sb + A_OFF + (uint32_t)((wm * 32 + (lid & 15)) * PITCH + (lid >> 4) * 16);
    const uint32_t bLd = sb + B_OFF + (uint32_t)((wn * 32 + (lid >> 4) * 8 + (lid & 7)) * PITCH
                                                 + ((lid >> 3) & 1) * 16);
    float acc[2][4][4];
    #pragma unroll
    for (int i = 0; i < 2; ++i)
        #pragma unroll
        for (int j = 0; j < 4; ++j)
            #pragma unroll
            for (int k = 0; k < 4; ++k) acc[i][j][k] = 0.f;

    float4 va[4];
    const int sflip = wid & 1;

    auto do_sts = [&](uint32_t nxt) {
        #pragma unroll
        for (int j = 0; j < 4; ++j) cvt_sts4h(nxt + aS + j * 16 * PITCH, va[j]);
    };
    auto do_cpb = [&](int kt2, uint32_t nxt) {   /* B stage via cp.async */
        const unsigned short* src = bGh + kt2 * KC;
        cp16(nxt + bS, src);
        cp16(nxt + bS + 16, src + 8);
        asm volatile("cp.async.commit_group;" ::: "memory");
    };
    auto do_ldg = [&](int kt2) {
        const float* a2 = aG + kt2 * KC;
        #pragma unroll
        for (int j = 0; j < 4; ++j) va[j] = *(const float4*)(a2 + j * 16 * D_);
    };
    auto do_mma = [&](uint32_t cur) {
        #pragma unroll
        for (int si = 0; si < 2; ++si) {
            const int s = si ^ sflip;
            uint32_t Ah[2][4], Bh[2][4];
            #pragma unroll
            for (int mt = 0; mt < 2; ++mt)
                ldsm4(Ah[mt], cur + aLd + mt * (16 * PITCH) + s * 32);
            #pragma unroll
            for (int h = 0; h < 2; ++h)
                ldsm4(Bh[h], cur + bLd + h * (16 * PITCH) + s * 32);
            #pragma unroll
            for (int mt = 0; mt < 2; ++mt)
                #pragma unroll
                for (int nt = 0; nt < 4; ++nt)
                    mma16816(acc[mt][nt], Ah[mt], &Bh[nt >> 1][(nt & 1) * 2]);
        }
    };

    /* prologue: stage 0 -> buf0 (A regs + B cp.async); prefetch A stage 1 */
    do_ldg(0);
    do_sts(0);
    do_cpb(0, 0);
    do_ldg(1);
    asm volatile("cp.async.wait_group 0;" ::: "memory");
    __syncthreads();

    for (int kt = 0; kt < NSTAGE; ++kt) {
        const uint32_t cur = (uint32_t)((kt & 1) * STAGE_B);
        const uint32_t nxt = (uint32_t)(((kt + 1) & 1) * STAGE_B);
        const bool haveN = (kt + 1 < NSTAGE);
        const bool haveN2 = (kt + 2 < NSTAGE);

        if ((wid & 1) == 0) {       /* even warps: stage first, compute second */
            if (haveN) { do_sts(nxt); do_cpb(kt + 1, nxt); }
            if (haveN2) do_ldg(kt + 2);
            do_mma(cur);
        } else {                    /* odd warps: compute first, stage second */
            do_mma(cur);
            if (haveN) { do_sts(nxt); do_cpb(kt + 1, nxt); }
            if (haveN2) do_ldg(kt + 2);
        }
        asm volatile("cp.async.wait_group 0;" ::: "memory");
        __syncthreads();
    }

    /* epilogue: fragments -> smem -> per-column max -> atomicMax */
    float* red = (float*)smem;   /* [64][66] = 16896 <= 20480 */
    const int g = lid >> 2, t = lid & 3;
    #pragma unroll
    for (int mt = 0; mt < 2; ++mt) {
        const int rw = wm * 32 + mt * 16 + g;
        #pragma unroll
        for (int nt = 0; nt < 4; ++nt) {
            const int c = wn * 32 + nt * 8 + t * 2;
            red[rw * 66 + c]           = acc[mt][nt][0];
            red[rw * 66 + c + 1]       = acc[mt][nt][1];
            red[(rw + 8) * 66 + c]     = acc[mt][nt][2];
            red[(rw + 8) * 66 + c + 1] = acc[mt][nt][3];
        }
    }
    __syncthreads();
    if (tid < 64) {
        float m = -3.4e38f;
        #pragma unroll 8
        for (int r = 0; r < TILE_M; ++r) m = fmaxf(m, red[r * 66 + tid]);
        unsigned int k = __float_as_uint(m);
        k = (k & 0x80000000u) ? ~k : (k | 0x80000000u);
        atomicMax(&g_key[b * B_ + tid], k);
    }
    __syncthreads();
    if (tid == 0) {
        __threadfence();
        s_last = (atomicAdd(&g_count, 1u) == NCTAS - 1);
    }
    __syncthreads();
    if (!s_last) return;
    __threadfence();   /* acquire: all producers' g_key writes now visible */

    /* ---- last CTA: decode simMax, hinge loss, reset globals ---- */
    float* sm = (float*)smem;          /* [64][65] */
    int*   lab = (int*)(smem + 64 * 65 * 4);
    for (int e = tid; e < B_ * B_; e += THREADS) {
        const unsigned int u = g_key[e];
        sm[(e >> 6) * 65 + (e & 63)] =
            __uint_as_float((u & 0x80000000u) ? (u ^ 0x80000000u) : ~u);
    }
    if (tid < 32) {   /* int64 labels (values <64) have zero odd int32 words */
        int odd = ((const int*)lblRaw)[2 * tid + 1];
        unsigned mm = __ballot_sync(0xFFFFFFFFu, odd != 0);
        if (tid == 0) s_is64 = (mm == 0u);
    }
    __syncthreads();
    if (tid < B_)
        lab[tid] = s_is64 ? (int)((const long long*)lblRaw)[tid] : ((const int*)lblRaw)[tid];
    __syncthreads();
    for (int e = tid; e < B_ * B_; e += THREADS) g_key[e] = 0u;   /* reset */
    if (tid == 0) g_count = 0u;

    float s1 = 0.f, s2v = 0.f, n = 0.f;
    for (int e = tid; e < B_ * B_; e += THREADS) {
        const int i = e >> 6, j = e & 63;
        if (lab[i] != lab[j]) {
            n += 1.f;
            const float p = sm[i * 65 + i];
            s1  += fmaxf(sm[i * 65 + j] - p + 0.1f, 0.f);
            s2v += fmaxf(sm[j * 65 + i] - p + 0.1f, 0.f);
        }
    }
    #pragma unroll
    for (int o = 16; o > 0; o >>= 1) {
        s1  += __shfl_down_sync(0xFFFFFFFFu, s1, o);
        s2v += __shfl_down_sync(0xFFFFFFFFu, s2v, o);
        n   += __shfl_down_sync(0xFFFFFFFFu, n, o);
    }
    if (lid == 0) { rr[0][wid] = s1; rr[1][wid] = s2v; rr[2][wid] = n; }
    __syncthreads();
    if (tid == 0) {
        float a = 0.f, c = 0.f, d = 0.f;
        #pragma unroll
        for (int w = 0; w < 4; ++w) { a += rr[0][w]; c += rr[1][w]; d += rr[2][w]; }
        out[0] = (a + c) / (d + 1e-6f);
    }
}

extern "C" void kernel_launch(void* const* d_in, const int* in_sizes, int n_in,
                              void* d_out, int out_size) {
    (void)in_sizes; (void)n_in; (void)out_size;
    const float* im  = (const float*)d_in[0];
    const float* dis = (const float*)d_in[1];
    const void*  lbl = d_in[2];

    cudaFuncSetAttribute(fused_kernel, cudaFuncAttributeMaxDynamicSharedMemorySize, SMEM_BYTES);
    convb_kernel<<<32, 256>>>(dis);
    dim3 grid(P_ / TILE_M, B_);
    fused_kernel<<<grid, THREADS, SMEM_BYTES>>>(im, lbl, (float*)d_out);
}